// round 3
// baseline (speedup 1.0000x reference)
#include <cuda_runtime.h>
#include <math.h>

#define BB   4
#define SQL  512
#define SKL  512
#define DD   512
#define HH   8
#define DHH  64
#define BHH  32
#define MR   2048

__device__ float g_qh[MR * DD];
__device__ float g_kh[MR * DD];
__device__ float g_vh[MR * DD];
__device__ float g_T [SQL * BHH * DD];   // [q][bh][e]
__device__ float g_c [MR * HH];
__device__ float g_att[MR * DD];
__device__ float g_o2 [MR * DD];

__device__ unsigned char g_am [SQL * SKL];
__device__ unsigned char g_kpm[BB * SKL];
__device__ int g_mask_mode;

// all 4 bytes of word nonzero?
__device__ __forceinline__ int bytes_all_nz(unsigned int v)
{
    return (((v - 0x01010101u) & ~v) & 0x80808080u) == 0u;
}

// ---------------------------------------------------------------------------
__global__ void mask_detect(const unsigned char* __restrict__ am)
{
    unsigned int or1 = 0, or23 = 0;
    const uint4* p = (const uint4*)am;
    int n16 = SQL * SKL / 16;
    for (int i = threadIdx.x; i < n16; i += blockDim.x) {
        uint4 v = p[i];
        or1  |= (v.x & 0x0000FF00u) | (v.y & 0x0000FF00u) | (v.z & 0x0000FF00u) | (v.w & 0x0000FF00u);
        or23 |= (v.x & 0xFFFF0000u) | (v.y & 0xFFFF0000u) | (v.z & 0xFFFF0000u) | (v.w & 0xFFFF0000u);
    }
    int any1  = __syncthreads_or((int)(or1 != 0));
    int any23 = __syncthreads_or((int)(or23 != 0));
    if (threadIdx.x == 0) g_mask_mode = any1 ? 1 : (any23 ? 2 : 0);
}

__global__ void mask_convert(const unsigned char* __restrict__ am,
                             const unsigned char* __restrict__ kpm)
{
    int mode = g_mask_mode;
    int stride = gridDim.x * blockDim.x;
    int tid = blockIdx.x * blockDim.x + threadIdx.x;
    for (int i = tid; i < SQL * SKL; i += stride) {
        unsigned char v;
        if (mode == 1)      v = (am[i] != 0);
        else if (mode == 2) v = (((const float*)am)[i] != 0.0f);
        else                v = (((const int*)am)[i] != 0);
        g_am[i] = v;
    }
    for (int i = tid; i < BB * SKL; i += stride) {
        unsigned char v;
        if (mode == 1)      v = (kpm[i] != 0);
        else if (mode == 2) v = (((const float*)kpm)[i] != 0.0f);
        else                v = (((const int*)kpm)[i] != 0);
        g_kpm[i] = v;
    }
}

// ---------------------------------------------------------------------------
// SGEMM: C[M,N] = A[M,K] @ W[K,N] + bias (+resid). BM=128 BN=64 BK=16.
// 256 threads, 8x4 per thread.
// ---------------------------------------------------------------------------
__global__ void sgemm_bias(const float* __restrict__ A, const float* __restrict__ W,
                           const float* __restrict__ bias, const float* __restrict__ resid,
                           float* __restrict__ C, int M, int N, int K)
{
    __shared__ float As[16][132];   // [k][m]
    __shared__ float Ws[16][64];    // [k][n]
    int tid = threadIdx.x;
    int tx = tid & 15, ty = tid >> 4;
    int row0 = blockIdx.y * 128;
    int col0 = blockIdx.x * 64;
    float acc[8][4] = {};

    int la_r = tid >> 2;
    int la_c = (tid & 3) * 4;
    int lw_r = tid >> 4;
    int lw_c = (tid & 15) * 4;

    for (int k0 = 0; k0 < K; k0 += 16) {
        #pragma unroll
        for (int rr = 0; rr < 2; rr++) {
            float4 a4 = *(const float4*)(A + (size_t)(row0 + la_r + rr * 64) * K + k0 + la_c);
            As[la_c + 0][la_r + rr * 64] = a4.x;
            As[la_c + 1][la_r + rr * 64] = a4.y;
            As[la_c + 2][la_r + rr * 64] = a4.z;
            As[la_c + 3][la_r + rr * 64] = a4.w;
        }
        float4 w4 = *(const float4*)(W + (size_t)(k0 + lw_r) * N + col0 + lw_c);
        *(float4*)&Ws[lw_r][lw_c] = w4;
        __syncthreads();
        #pragma unroll
        for (int kk = 0; kk < 16; kk++) {
            float a[8], b[4];
            *(float4*)(a)     = *(float4*)&As[kk][ty * 8];
            *(float4*)(a + 4) = *(float4*)&As[kk][ty * 8 + 4];
            *(float4*)(b)     = *(float4*)&Ws[kk][tx * 4];
            #pragma unroll
            for (int i = 0; i < 8; i++)
                #pragma unroll
                for (int j = 0; j < 4; j++)
                    acc[i][j] += a[i] * b[j];
        }
        __syncthreads();
    }
    float4 b4 = *(const float4*)(bias + col0 + tx * 4);
    #pragma unroll
    for (int i = 0; i < 8; i++) {
        int r = row0 + ty * 8 + i;
        float4 vv = {acc[i][0] + b4.x, acc[i][1] + b4.y, acc[i][2] + b4.z, acc[i][3] + b4.w};
        if (resid) {
            float4 r4 = *(const float4*)(resid + (size_t)r * N + col0 + tx * 4);
            vv.x += r4.x; vv.y += r4.y; vv.z += r4.z; vv.w += r4.w;
        }
        *(float4*)(C + (size_t)r * N + col0 + tx * 4) = vv;
    }
}

// ---------------------------------------------------------------------------
// t[b,q,h,e] = sum_d (qh+v_bias)*Wr[e,hoff+d]. BM=128(m) BN=64(e) BK=16, per h.
// ---------------------------------------------------------------------------
__global__ void t_kernel(const float* __restrict__ Wr, const float* __restrict__ vb)
{
    __shared__ float As[16][132];   // [d][m]
    __shared__ float Ws[16][64];    // [d][e]
    int h = blockIdx.z, hoff = h * DHH;
    int m0 = blockIdx.y * 128, e0 = blockIdx.x * 64;
    int tid = threadIdx.x;
    int tx = tid & 15, ty = tid >> 4;
    float acc[8][4] = {};

    int la_r = tid >> 2;
    int la_c = (tid & 3) * 4;

    for (int d0 = 0; d0 < DHH; d0 += 16) {
        float4 v4 = *(const float4*)(vb + hoff + d0 + la_c);
        #pragma unroll
        for (int rr = 0; rr < 2; rr++) {
            float4 a4 = *(const float4*)(g_qh + (size_t)(m0 + la_r + rr * 64) * DD + hoff + d0 + la_c);
            As[la_c + 0][la_r + rr * 64] = a4.x + v4.x;
            As[la_c + 1][la_r + rr * 64] = a4.y + v4.y;
            As[la_c + 2][la_r + rr * 64] = a4.z + v4.z;
            As[la_c + 3][la_r + rr * 64] = a4.w + v4.w;
        }
        // Wr rows e0..e0+63, cols hoff+d0..+16 -> transposed
        float4 w4 = *(const float4*)(Wr + (size_t)(e0 + la_r) * DD + hoff + d0 + la_c);
        Ws[la_c + 0][la_r] = w4.x;
        Ws[la_c + 1][la_r] = w4.y;
        Ws[la_c + 2][la_r] = w4.z;
        Ws[la_c + 3][la_r] = w4.w;
        __syncthreads();
        #pragma unroll
        for (int kk = 0; kk < 16; kk++) {
            float a[8], b[4];
            *(float4*)(a)     = *(float4*)&As[kk][ty * 8];
            *(float4*)(a + 4) = *(float4*)&As[kk][ty * 8 + 4];
            *(float4*)(b)     = *(float4*)&Ws[kk][tx * 4];
            #pragma unroll
            for (int i = 0; i < 8; i++)
                #pragma unroll
                for (int j = 0; j < 4; j++)
                    acc[i][j] += a[i] * b[j];
        }
        __syncthreads();
    }
    #pragma unroll
    for (int i = 0; i < 8; i++) {
        int mm = m0 + ty * 8 + i;
        int b = mm >> 9, qq = mm & 511;
        float4 sv = {acc[i][0], acc[i][1], acc[i][2], acc[i][3]};
        *(float4*)(g_T + ((size_t)qq * BHH + b * HH + h) * DD + e0 + tx * 4) = sv;
    }
}

// c[b,q,h] = sum_d (qh+v_bias)*br_h
__global__ void c_kernel(const float* __restrict__ vb, const float* __restrict__ br)
{
    int idx = blockIdx.x * blockDim.x + threadIdx.x;
    if (idx >= MR * HH) return;
    int h = idx & 7;
    int m = idx >> 3;
    int hoff = h * DHH;
    const float* qrow = g_qh + (size_t)m * DD + hoff;
    float s = 0.f;
    #pragma unroll 8
    for (int d = 0; d < DHH; d++)
        s += (qrow[d] + vb[hoff + d]) * br[hoff + d];
    g_c[idx] = s;
}

// ---------------------------------------------------------------------------
// ac: score[bh,q,k] = sum_d (qh+u)*kh. BM=128(q) BN=64(k) BK=16, K=64.
// ---------------------------------------------------------------------------
__global__ void ac_kernel(const float* __restrict__ ub, float* __restrict__ score)
{
    __shared__ float As[16][132];   // [d][q]
    __shared__ float Ks[16][64];    // [d][k]
    int bh = blockIdx.z, b = bh >> 3, h = bh & 7, hoff = h * DHH;
    int q0 = blockIdx.y * 128, k0 = blockIdx.x * 64;
    int tid = threadIdx.x;
    int tx = tid & 15, ty = tid >> 4;

    {   // full-tile mask check: 128 rows x 64 bytes; 32 bytes/thread
        const uint4* mp = (const uint4*)(g_am + (size_t)(q0 + (tid >> 1)) * SKL + k0 + (tid & 1) * 32);
        uint4 m1 = mp[0], m2 = mp[1];
        int allm = bytes_all_nz(m1.x) & bytes_all_nz(m1.y) & bytes_all_nz(m1.z) & bytes_all_nz(m1.w)
                 & bytes_all_nz(m2.x) & bytes_all_nz(m2.y) & bytes_all_nz(m2.z) & bytes_all_nz(m2.w);
        if (__syncthreads_and(allm)) return;
    }

    int la_r = tid >> 2;
    int la_c = (tid & 3) * 4;
    float acc[8][4] = {};

    for (int d0 = 0; d0 < DHH; d0 += 16) {
        float4 u4 = *(const float4*)(ub + hoff + d0 + la_c);
        #pragma unroll
        for (int rr = 0; rr < 2; rr++) {
            float4 a4 = *(const float4*)(g_qh + ((size_t)b * SQL + q0 + la_r + rr * 64) * DD + hoff + d0 + la_c);
            As[la_c + 0][la_r + rr * 64] = a4.x + u4.x;
            As[la_c + 1][la_r + rr * 64] = a4.y + u4.y;
            As[la_c + 2][la_r + rr * 64] = a4.z + u4.z;
            As[la_c + 3][la_r + rr * 64] = a4.w + u4.w;
        }
        float4 k4 = *(const float4*)(g_kh + ((size_t)b * SQL + k0 + la_r) * DD + hoff + d0 + la_c);
        Ks[la_c + 0][la_r] = k4.x;
        Ks[la_c + 1][la_r] = k4.y;
        Ks[la_c + 2][la_r] = k4.z;
        Ks[la_c + 3][la_r] = k4.w;
        __syncthreads();
        #pragma unroll
        for (int kk = 0; kk < 16; kk++) {
            float a[8], bv[4];
            *(float4*)(a)      = *(float4*)&As[kk][ty * 8];
            *(float4*)(a + 4)  = *(float4*)&As[kk][ty * 8 + 4];
            *(float4*)(bv)     = *(float4*)&Ks[kk][tx * 4];
            #pragma unroll
            for (int i = 0; i < 8; i++)
                #pragma unroll
                for (int j = 0; j < 4; j++)
                    acc[i][j] += a[i] * bv[j];
        }
        __syncthreads();
    }
    #pragma unroll
    for (int i = 0; i < 8; i++) {
        float4 sv = {acc[i][0], acc[i][1], acc[i][2], acc[i][3]};
        *(float4*)(score + ((size_t)bh * SQL + q0 + ty * 8 + i) * SKL + k0 + tx * 4) = sv;
    }
}

// ---------------------------------------------------------------------------
// bd: score[bh,q,k] = (ac + sum_e T[q][bh][e]*pos[q,k,e] + c)/8.
// Block: one q, 128-k tile, all 32 bh. 2bh x 8k per thread.
// ---------------------------------------------------------------------------
__global__ void bd_kernel(const float* __restrict__ pos_emb, float* __restrict__ score)
{
    const int EC = 32;
    __shared__ float Ts[EC][36];     // [e][bh]
    __shared__ float Ps[EC][132];    // [e][k]
    int q = blockIdx.y;
    int k0 = blockIdx.x * 128;
    int tid = threadIdx.x;

    int myb = (tid < 128) ? (g_am[(size_t)q * SKL + k0 + tid] != 0) : 1;
    if (__syncthreads_and(myb)) return;

    int kg = tid & 15;
    int bg = tid >> 4;
    float acc0[8] = {}, acc1[8] = {};

    const float* Tbase = g_T + (size_t)q * BHH * DD;
    const float* Pbase = pos_emb + ((size_t)q * SKL + k0) * DD;
    int lr = tid >> 3;          // 0..31
    int le = (tid & 7) * 4;     // 0..28

    for (int e0 = 0; e0 < DD; e0 += EC) {
        float4 t4 = *(const float4*)(Tbase + (size_t)lr * DD + e0 + le);
        Ts[le + 0][lr] = t4.x; Ts[le + 1][lr] = t4.y;
        Ts[le + 2][lr] = t4.z; Ts[le + 3][lr] = t4.w;
        #pragma unroll
        for (int rr = 0; rr < 4; rr++) {
            int kr = lr + rr * 32;
            float4 p4 = *(const float4*)(Pbase + (size_t)kr * DD + e0 + le);
            Ps[le + 0][kr] = p4.x; Ps[le + 1][kr] = p4.y;
            Ps[le + 2][kr] = p4.z; Ps[le + 3][kr] = p4.w;
        }
        __syncthreads();
        #pragma unroll
        for (int e = 0; e < EC; e++) {
            float a0 = Ts[e][bg * 2 + 0];
            float a1 = Ts[e][bg * 2 + 1];
            float b[8];
            *(float4*)(b)     = *(float4*)&Ps[e][kg * 8];
            *(float4*)(b + 4) = *(float4*)&Ps[e][kg * 8 + 4];
            #pragma unroll
            for (int j = 0; j < 8; j++) {
                acc0[j] += a0 * b[j];
                acc1[j] += a1 * b[j];
            }
        }
        __syncthreads();
    }

    #pragma unroll
    for (int i = 0; i < 2; i++) {
        int bh = bg * 2 + i;
        int b = bh >> 3, h = bh & 7;
        float cc = g_c[((size_t)b * SQL + q) * HH + h];
        float* acc = i ? acc1 : acc0;
        float* srow = score + ((size_t)bh * SQL + q) * SKL + k0 + kg * 8;
        float4 s0 = *(float4*)srow;
        float4 s1 = *(float4*)(srow + 4);
        s0.x = (s0.x + acc[0] + cc) * 0.125f;
        s0.y = (s0.y + acc[1] + cc) * 0.125f;
        s0.z = (s0.z + acc[2] + cc) * 0.125f;
        s0.w = (s0.w + acc[3] + cc) * 0.125f;
        s1.x = (s1.x + acc[4] + cc) * 0.125f;
        s1.y = (s1.y + acc[5] + cc) * 0.125f;
        s1.z = (s1.z + acc[6] + cc) * 0.125f;
        s1.w = (s1.w + acc[7] + cc) * 0.125f;
        *(float4*)srow = s0;
        *(float4*)(srow + 4) = s1;
    }
}

// ---------------------------------------------------------------------------
__global__ void softmax_kernel(float* __restrict__ score)
{
    int row = blockIdx.x;
    int q = row & 511;
    int bh = row >> 9;
    int b = bh >> 3;
    int tid = threadIdx.x;         // 128
    float* s = score + (size_t)row * SKL;

    float4 v4 = *(float4*)(s + tid * 4);
    float vals[4] = {v4.x, v4.y, v4.z, v4.w};
    const unsigned char* amr = g_am + (size_t)q * SKL + tid * 4;
    const unsigned char* kpr = g_kpm + (size_t)b * SKL + tid * 4;
    #pragma unroll
    for (int j = 0; j < 4; j++)
        if (amr[j] || kpr[j]) vals[j] = -INFINITY;

    float mx = fmaxf(fmaxf(vals[0], vals[1]), fmaxf(vals[2], vals[3]));
    #pragma unroll
    for (int off = 16; off; off >>= 1)
        mx = fmaxf(mx, __shfl_xor_sync(0xffffffffu, mx, off));
    __shared__ float sm[4], ssum[4];
    int wid = tid >> 5, lane = tid & 31;
    if (lane == 0) sm[wid] = mx;
    __syncthreads();
    mx = fmaxf(fmaxf(sm[0], sm[1]), fmaxf(sm[2], sm[3]));

    float e[4]; float sum = 0.f;
    #pragma unroll
    for (int j = 0; j < 4; j++) {
        e[j] = (vals[j] == -INFINITY) ? 0.f : __expf(vals[j] - mx);
        sum += e[j];
    }
    #pragma unroll
    for (int off = 16; off; off >>= 1)
        sum += __shfl_xor_sync(0xffffffffu, sum, off);
    if (lane == 0) ssum[wid] = sum;
    __syncthreads();
    sum = ssum[0] + ssum[1] + ssum[2] + ssum[3];
    float inv = (sum > 0.f) ? 1.f / sum : 0.f;
    float4 o = {e[0] * inv, e[1] * inv, e[2] * inv, e[3] * inv};
    *(float4*)(s + tid * 4) = o;
}

// ---------------------------------------------------------------------------
// AV: att[b,q,h,d] = sum_k w[bh,q,k]*vh[b,k,h,d]. BM=128(q) BN=64(d) BK=16.
// ---------------------------------------------------------------------------
__global__ void av_kernel(const float* __restrict__ score)
{
    __shared__ float As[16][132];   // [k][q]
    __shared__ float Vs[16][64];    // [k][d]
    int bh = blockIdx.y, b = bh >> 3, h = bh & 7, hoff = h * DHH;
    int q0 = blockIdx.x * 128;
    int tid = threadIdx.x;
    int tx = tid & 15, ty = tid >> 4;
    float acc[8][4] = {};

    int la_r = tid >> 2;
    int la_c = (tid & 3) * 4;

    for (int k0 = 0; k0 < SKL; k0 += 16) {
        // chunk mask check: 128 rows x 16 bytes; 8 bytes/thread
        const unsigned int* mp = (const unsigned int*)(g_am + (size_t)(q0 + (tid >> 1)) * SKL + k0 + (tid & 1) * 8);
        int allm = bytes_all_nz(mp[0]) & bytes_all_nz(mp[1]);
        if (__syncthreads_and(allm)) continue;

        #pragma unroll
        for (int rr = 0; rr < 2; rr++) {
            float4 a4 = *(const float4*)(score + ((size_t)bh * SQL + q0 + la_r + rr * 64) * SKL + k0 + la_c);
            As[la_c + 0][la_r + rr * 64] = a4.x;
            As[la_c + 1][la_r + rr * 64] = a4.y;
            As[la_c + 2][la_r + rr * 64] = a4.z;
            As[la_c + 3][la_r + rr * 64] = a4.w;
        }
        int lw_r = tid >> 4, lw_c = (tid & 15) * 4;
        float4 w4 = *(const float4*)(g_vh + ((size_t)b * SQL + k0 + lw_r) * DD + hoff + lw_c);
        *(float4*)&Vs[lw_r][lw_c] = w4;
        __syncthreads();
        #pragma unroll
        for (int kk = 0; kk < 16; kk++) {
            float a[8], bv[4];
            *(float4*)(a)      = *(float4*)&As[kk][ty * 8];
            *(float4*)(a + 4)  = *(float4*)&As[kk][ty * 8 + 4];
            *(float4*)(bv)     = *(float4*)&Vs[kk][tx * 4];
            #pragma unroll
            for (int i = 0; i < 8; i++)
                #pragma unroll
                for (int j = 0; j < 4; j++)
                    acc[i][j] += a[i] * bv[j];
        }
        __syncthreads();
    }
    #pragma unroll
    for (int i = 0; i < 8; i++) {
        float4 sv = {acc[i][0], acc[i][1], acc[i][2], acc[i][3]};
        *(float4*)(g_att + ((size_t)b * SQL + q0 + ty * 8 + i) * DD + hoff + tx * 4) = sv;
    }
}

// ---------------------------------------------------------------------------
__global__ void ln_kernel(const float* __restrict__ X, const float* __restrict__ gamma,
                          const float* __restrict__ beta, float* __restrict__ out)
{
    int row = blockIdx.x;
    int tid = threadIdx.x;  // 256
    const float* x = X + (size_t)row * DD;
    float2 v = *(const float2*)(x + tid * 2);
    float s = v.x + v.y;
    float s2 = v.x * v.x + v.y * v.y;
    #pragma unroll
    for (int off = 16; off; off >>= 1) {
        s  += __shfl_xor_sync(0xffffffffu, s, off);
        s2 += __shfl_xor_sync(0xffffffffu, s2, off);
    }
    __shared__ float rs[8], rs2[8];
    int wid = tid >> 5, lane = tid & 31;
    if (lane == 0) { rs[wid] = s; rs2[wid] = s2; }
    __syncthreads();
    s = 0.f; s2 = 0.f;
    #pragma unroll
    for (int i = 0; i < 8; i++) { s += rs[i]; s2 += rs2[i]; }
    float mean = s * (1.f / DD);
    float var = s2 * (1.f / DD) - mean * mean;
    float inv = rsqrtf(var + 1e-5f);
    float2 g2 = *(const float2*)(gamma + tid * 2);
    float2 b2 = *(const float2*)(beta + tid * 2);
    float2 o;
    o.x = (v.x - mean) * inv * g2.x + b2.x;
    o.y = (v.y - mean) * inv * g2.y + b2.y;
    *(float2*)(out + (size_t)row * DD + tid * 2) = o;
}

// ---------------------------------------------------------------------------
extern "C" void kernel_launch(void* const* d_in, const int* in_sizes, int n_in,
                              void* d_out, int out_size)
{
    const float* q  = (const float*)d_in[0];
    const float* k  = (const float*)d_in[1];
    const float* v  = (const float*)d_in[2];
    const float* pe = (const float*)d_in[3];
    const unsigned char* kpm = (const unsigned char*)d_in[4];
    const unsigned char* am  = (const unsigned char*)d_in[5];
    const float* Wq = (const float*)d_in[6];
    const float* bq = (const float*)d_in[7];
    const float* Wk = (const float*)d_in[8];
    const float* bk = (const float*)d_in[9];
    const float* Wv = (const float*)d_in[10];
    const float* bv = (const float*)d_in[11];
    const float* Wo = (const float*)d_in[12];
    const float* bo = (const float*)d_in[13];
    const float* Wr = (const float*)d_in[14];
    const float* br = (const float*)d_in[15];
    const float* ub = (const float*)d_in[16];
    const float* vb = (const float*)d_in[17];
    const float* lg = (const float*)d_in[18];
    const float* lb = (const float*)d_in[19];

    float* normed = (float*)d_out;
    float* attnw  = normed + (size_t)BB * SQL * DD;

    float *qh, *kh, *vh, *att, *o2;
    cudaGetSymbolAddress((void**)&qh,  g_qh);
    cudaGetSymbolAddress((void**)&kh,  g_kh);
    cudaGetSymbolAddress((void**)&vh,  g_vh);
    cudaGetSymbolAddress((void**)&att, g_att);
    cudaGetSymbolAddress((void**)&o2,  g_o2);

    mask_detect<<<1, 1024>>>(am);
    mask_convert<<<64, 256>>>(am, kpm);

    sgemm_bias<<<dim3(8, 16), 256>>>(q, Wq, bq, nullptr, qh, MR, DD, DD);
    sgemm_bias<<<dim3(8, 16), 256>>>(k, Wk, bk, nullptr, kh, MR, DD, DD);
    sgemm_bias<<<dim3(8, 16), 256>>>(v, Wv, bv, nullptr, vh, MR, DD, DD);

    c_kernel<<<(MR * HH + 255) / 256, 256>>>(vb, br);
    t_kernel<<<dim3(8, 16, 8), 256>>>(Wr, vb);

    ac_kernel<<<dim3(8, 4, 32), 256>>>(ub, attnw);
    bd_kernel<<<dim3(4, 512), 256>>>(pe, attnw);
    softmax_kernel<<<BHH * SQL, 128>>>(attnw);

    av_kernel<<<dim3(4, 32), 256>>>(attnw);

    sgemm_bias<<<dim3(8, 16), 256>>>(att, Wo, bo, q, o2, MR, DD, DD);
    ln_kernel<<<MR, 256>>>(o2, lg, lb, normed);
}

// round 5
// speedup vs baseline: 1.3528x; 1.3528x over previous
#include <cuda_runtime.h>
#include <cuda_bf16.h>
#include <math.h>
#include <stdint.h>

#define BB   4
#define SQL  512
#define SKL  512
#define DD   512
#define HH   8
#define DHH  64
#define BHH  32
#define MR   2048

__device__ float g_qh[MR * DD];
__device__ float g_kh[MR * DD];
__device__ float g_vh[MR * DD];
__device__ float g_T [SQL * BHH * DD];   // [q][bh][e]
__device__ float g_c [MR * HH];
__device__ float g_att[MR * DD];
__device__ float g_o2 [MR * DD];

__device__ unsigned char g_am [SQL * SKL];
__device__ unsigned char g_kpm[BB * SKL];
__device__ int g_mask_mode;

// ===========================================================================
// bf16 helpers
// ===========================================================================
__device__ __forceinline__ uint32_t pack_bf16x2(float x, float y) {
    uint32_t r;
    asm("cvt.rn.bf16x2.f32 %0, %1, %2;" : "=r"(r) : "f"(y), "f"(x));
    return r;
}

#define MMA_BF16(c, a, b0, b1) \
    asm volatile("mma.sync.aligned.m16n8k16.row.col.f32.bf16.bf16.f32 " \
        "{%0,%1,%2,%3}, {%4,%5,%6,%7}, {%8,%9}, {%0,%1,%2,%3};" \
        : "+f"((c)[0]), "+f"((c)[1]), "+f"((c)[2]), "+f"((c)[3]) \
        : "r"((a)[0]), "r"((a)[1]), "r"((a)[2]), "r"((a)[3]), "r"(b0), "r"(b1))

// ===========================================================================
// Tensor-core GEMM via mma.sync (bf16 hi/lo split => ~fp32 accuracy).
// C[2048,512] = A[2048,512] @ W[512,512] + bias (+resid).
// BM=128 BN=64 BK=32, 256 threads = 8 warps (4m x 2n), warp tile 32x32.
// ===========================================================================
#define MG_AS 40   // smem row stride (bf16 elems)
__global__ void __launch_bounds__(256, 1)
mma_gemm(const float* __restrict__ A, const float* __restrict__ W,
         const float* __restrict__ bias, const float* __restrict__ resid,
         float* __restrict__ C)
{
    __shared__ __nv_bfloat16 Ah[128][MG_AS], Al[128][MG_AS];
    __shared__ __nv_bfloat16 Bh[64][MG_AS],  Bl[64][MG_AS];

    int tid = threadIdx.x;
    int wid = tid >> 5, lane = tid & 31;
    int wm = wid >> 1, wn = wid & 1;
    int row0 = blockIdx.y * 128;
    int n0 = blockIdx.x * 64;

    float acc[2][4][4] = {};

    int ar = tid >> 1;               // 0..127  (A row)
    int ac0 = (tid & 1) * 16;        // 0/16    (A col base)
    int bk = tid >> 4;               // 0..15   (B k row)
    int bn0 = (tid & 15) * 4;        // 0..60   (B n base)
    int r = lane >> 2, t4 = lane & 3;

    for (int k0 = 0; k0 < DD; k0 += 32) {
        // ---- fill A tile (hi/lo) ----
        const float* Ap = A + (size_t)(row0 + ar) * DD + k0 + ac0;
        #pragma unroll
        for (int i = 0; i < 4; i++) {
            float4 a = *(const float4*)(Ap + i * 4);
            float av[4] = {a.x, a.y, a.z, a.w};
            #pragma unroll
            for (int j = 0; j < 4; j++) {
                __nv_bfloat16 hb = __float2bfloat16_rn(av[j]);
                __nv_bfloat16 lb = __float2bfloat16_rn(av[j] - __bfloat162float(hb));
                Ah[ar][ac0 + i * 4 + j] = hb;
                Al[ar][ac0 + i * 4 + j] = lb;
            }
        }
        // ---- fill B tile transposed: Bs[n][k] = W[k0+k][n0+n] ----
        #pragma unroll
        for (int i = 0; i < 2; i++) {
            int kk = bk + i * 16;
            float4 w = *(const float4*)(W + (size_t)(k0 + kk) * DD + n0 + bn0);
            float wv[4] = {w.x, w.y, w.z, w.w};
            #pragma unroll
            for (int j = 0; j < 4; j++) {
                __nv_bfloat16 hb = __float2bfloat16_rn(wv[j]);
                __nv_bfloat16 lb = __float2bfloat16_rn(wv[j] - __bfloat162float(hb));
                Bh[bn0 + j][kk] = hb;
                Bl[bn0 + j][kk] = lb;
            }
        }
        __syncthreads();

        // ---- 2 k16 steps ----
        #pragma unroll
        for (int ks = 0; ks < 2; ks++) {
            uint32_t ah[2][4], al[2][4];
            #pragma unroll
            for (int mi = 0; mi < 2; mi++) {
                int row = wm * 32 + mi * 16 + r;
                const __nv_bfloat16* ph = &Ah[row][ks * 16 + t4 * 2];
                const __nv_bfloat16* pl = &Al[row][ks * 16 + t4 * 2];
                ah[mi][0] = *(const uint32_t*)ph;
                ah[mi][1] = *(const uint32_t*)(ph + 8 * MG_AS);
                ah[mi][2] = *(const uint32_t*)(ph + 8);
                ah[mi][3] = *(const uint32_t*)(ph + 8 * MG_AS + 8);
                al[mi][0] = *(const uint32_t*)pl;
                al[mi][1] = *(const uint32_t*)(pl + 8 * MG_AS);
                al[mi][2] = *(const uint32_t*)(pl + 8);
                al[mi][3] = *(const uint32_t*)(pl + 8 * MG_AS + 8);
            }
            #pragma unroll
            for (int nj = 0; nj < 4; nj++) {
                int n = wn * 32 + nj * 8 + r;
                const __nv_bfloat16* qh = &Bh[n][ks * 16 + t4 * 2];
                const __nv_bfloat16* ql = &Bl[n][ks * 16 + t4 * 2];
                uint32_t bh0 = *(const uint32_t*)qh;
                uint32_t bh1 = *(const uint32_t*)(qh + 8);
                uint32_t bl0 = *(const uint32_t*)ql;
                uint32_t bl1 = *(const uint32_t*)(ql + 8);
                #pragma unroll
                for (int mi = 0; mi < 2; mi++) {
                    MMA_BF16(acc[mi][nj], ah[mi], bh0, bh1);
                    MMA_BF16(acc[mi][nj], ah[mi], bl0, bl1);
                    MMA_BF16(acc[mi][nj], al[mi], bh0, bh1);
                }
            }
        }
        __syncthreads();
    }

    // ---- epilogue ----
    #pragma unroll
    for (int mi = 0; mi < 2; mi++) {
        #pragma unroll
        for (int nj = 0; nj < 4; nj++) {
            int row = row0 + wm * 32 + mi * 16 + r;
            int col = n0 + wn * 32 + nj * 8 + t4 * 2;
            float b0 = bias[col], b1 = bias[col + 1];
            float2 o0 = {acc[mi][nj][0] + b0, acc[mi][nj][1] + b1};
            float2 o1 = {acc[mi][nj][2] + b0, acc[mi][nj][3] + b1};
            if (resid) {
                float2 r0 = *(const float2*)(resid + (size_t)row * DD + col);
                float2 r1 = *(const float2*)(resid + (size_t)(row + 8) * DD + col);
                o0.x += r0.x; o0.y += r0.y;
                o1.x += r1.x; o1.y += r1.y;
            }
            *(float2*)(C + (size_t)row * DD + col) = o0;
            *(float2*)(C + (size_t)(row + 8) * DD + col) = o1;
        }
    }
}

// ===========================================================================
// Mask normalization (dtype-agnostic)
// ===========================================================================
__global__ void mask_detect(const unsigned char* __restrict__ am)
{
    unsigned int or1 = 0, or23 = 0;
    const uint4* p = (const uint4*)am;
    int n16 = SQL * SKL / 16;
    for (int i = threadIdx.x; i < n16; i += blockDim.x) {
        uint4 v = p[i];
        or1  |= (v.x & 0x0000FF00u) | (v.y & 0x0000FF00u) | (v.z & 0x0000FF00u) | (v.w & 0x0000FF00u);
        or23 |= (v.x & 0xFFFF0000u) | (v.y & 0xFFFF0000u) | (v.z & 0xFFFF0000u) | (v.w & 0xFFFF0000u);
    }
    int any1  = __syncthreads_or((int)(or1 != 0));
    int any23 = __syncthreads_or((int)(or23 != 0));
    if (threadIdx.x == 0) g_mask_mode = any1 ? 1 : (any23 ? 2 : 0);
}

__global__ void mask_convert(const unsigned char* __restrict__ am,
                             const unsigned char* __restrict__ kpm)
{
    int mode = g_mask_mode;
    int stride = gridDim.x * blockDim.x;
    int tid = blockIdx.x * blockDim.x + threadIdx.x;
    for (int i = tid; i < SQL * SKL; i += stride) {
        unsigned char v;
        if (mode == 1)      v = (am[i] != 0);
        else if (mode == 2) v = (((const float*)am)[i] != 0.0f);
        else                v = (((const int*)am)[i] != 0);
        g_am[i] = v;
    }
    for (int i = tid; i < BB * SKL; i += stride) {
        unsigned char v;
        if (mode == 1)      v = (kpm[i] != 0);
        else if (mode == 2) v = (((const float*)kpm)[i] != 0.0f);
        else                v = (((const int*)kpm)[i] != 0);
        g_kpm[i] = v;
    }
}

// ===========================================================================
// R2 scalar kernels (known-good config)
// ===========================================================================
__global__ void t_kernel(const float* __restrict__ Wr, const float* __restrict__ vb)
{
    __shared__ float As[16][64];
    __shared__ float Ws[16][64];
    int h = blockIdx.z, hoff = h * DHH;
    int m0 = blockIdx.y * 64, e0 = blockIdx.x * 64;
    int tid = threadIdx.x;
    int tx = tid & 15, ty = tid >> 4;
    int lr = tid >> 2, lc = (tid & 3) * 4;
    float acc[4][4] = {};

    for (int d0 = 0; d0 < DHH; d0 += 16) {
        float4 a4 = *(const float4*)(g_qh + (size_t)(m0 + lr) * DD + hoff + d0 + lc);
        float4 v4 = *(const float4*)(vb + hoff + d0 + lc);
        As[lc + 0][lr] = a4.x + v4.x;
        As[lc + 1][lr] = a4.y + v4.y;
        As[lc + 2][lr] = a4.z + v4.z;
        As[lc + 3][lr] = a4.w + v4.w;
        float4 w4 = *(const float4*)(Wr + (size_t)(e0 + lr) * DD + hoff + d0 + lc);
        Ws[lc + 0][lr] = w4.x;
        Ws[lc + 1][lr] = w4.y;
        Ws[lc + 2][lr] = w4.z;
        Ws[lc + 3][lr] = w4.w;
        __syncthreads();
        #pragma unroll
        for (int kk = 0; kk < 16; kk++) {
            float a[4], b[4];
            #pragma unroll
            for (int i = 0; i < 4; i++) a[i] = As[kk][ty * 4 + i];
            #pragma unroll
            for (int j = 0; j < 4; j++) b[j] = Ws[kk][tx * 4 + j];
            #pragma unroll
            for (int i = 0; i < 4; i++)
                #pragma unroll
                for (int j = 0; j < 4; j++)
                    acc[i][j] += a[i] * b[j];
        }
        __syncthreads();
    }
    #pragma unroll
    for (int i = 0; i < 4; i++) {
        int mm = m0 + ty * 4 + i;
        int b = mm >> 9, qq = mm & 511;
        float4 sv = {acc[i][0], acc[i][1], acc[i][2], acc[i][3]};
        *(float4*)(g_T + ((size_t)qq * BHH + b * HH + h) * DD + e0 + tx * 4) = sv;
    }
}

__global__ void c_kernel(const float* __restrict__ vb, const float* __restrict__ br)
{
    int idx = blockIdx.x * blockDim.x + threadIdx.x;
    if (idx >= MR * HH) return;
    int h = idx & 7;
    int m = idx >> 3;
    int hoff = h * DHH;
    const float* qrow = g_qh + (size_t)m * DD + hoff;
    float s = 0.f;
    #pragma unroll 8
    for (int d = 0; d < DHH; d++)
        s += (qrow[d] + vb[hoff + d]) * br[hoff + d];
    g_c[idx] = s;
}

__global__ void ac_kernel(const float* __restrict__ ub, float* __restrict__ score)
{
    __shared__ float As[16][64];
    __shared__ float Ks[16][64];
    int bh = blockIdx.z, b = bh >> 3, h = bh & 7, hoff = h * DHH;
    int q0 = blockIdx.y * 64, k0 = blockIdx.x * 64;
    int tid = threadIdx.x;
    int tx = tid & 15, ty = tid >> 4;

    const unsigned char* rp = g_am + (size_t)(q0 + (tid >> 2)) * SKL + k0 + (tid & 3) * 16;
    int allm = 1;
    #pragma unroll
    for (int j = 0; j < 16; j++) allm &= (rp[j] != 0);
    if (__syncthreads_and(allm)) return;

    int lr = tid >> 2, lc = (tid & 3) * 4;
    float acc[4][4] = {};
    for (int d0 = 0; d0 < DHH; d0 += 16) {
        float4 a4 = *(const float4*)(g_qh + ((size_t)b * SQL + q0 + lr) * DD + hoff + d0 + lc);
        float4 u4 = *(const float4*)(ub + hoff + d0 + lc);
        As[lc + 0][lr] = a4.x + u4.x;
        As[lc + 1][lr] = a4.y + u4.y;
        As[lc + 2][lr] = a4.z + u4.z;
        As[lc + 3][lr] = a4.w + u4.w;
        float4 k4 = *(const float4*)(g_kh + ((size_t)b * SQL + k0 + lr) * DD + hoff + d0 + lc);
        Ks[lc + 0][lr] = k4.x;
        Ks[lc + 1][lr] = k4.y;
        Ks[lc + 2][lr] = k4.z;
        Ks[lc + 3][lr] = k4.w;
        __syncthreads();
        #pragma unroll
        for (int kk = 0; kk < 16; kk++) {
            float a[4], bv[4];
            #pragma unroll
            for (int i = 0; i < 4; i++) a[i] = As[kk][ty * 4 + i];
            #pragma unroll
            for (int j = 0; j < 4; j++) bv[j] = Ks[kk][tx * 4 + j];
            #pragma unroll
            for (int i = 0; i < 4; i++)
                #pragma unroll
                for (int j = 0; j < 4; j++)
                    acc[i][j] += a[i] * bv[j];
        }
        __syncthreads();
    }
    #pragma unroll
    for (int i = 0; i < 4; i++) {
        float4 sv = {acc[i][0], acc[i][1], acc[i][2], acc[i][3]};
        *(float4*)(score + ((size_t)bh * SQL + q0 + ty * 4 + i) * SKL + k0 + tx * 4) = sv;
    }
}

__global__ void bd_kernel(const float* __restrict__ pos_emb, float* __restrict__ score)
{
    const int EC = 32;
    __shared__ float Ts[32][EC + 1];
    __shared__ float Ps[64][EC + 1];
    int q = blockIdx.y;
    int k0 = blockIdx.x * 64;
    int tid = threadIdx.x;

    int allm = g_am[(size_t)q * SKL + k0 + (tid & 63)] != 0;
    if (__syncthreads_and(allm)) return;

    int kg = tid & 15;
    int bg = tid >> 4;
    float acc0[4] = {0.f, 0.f, 0.f, 0.f};
    float acc1[4] = {0.f, 0.f, 0.f, 0.f};

    const float* Tbase = g_T + (size_t)q * BHH * DD;
    const float* Pbase = pos_emb + ((size_t)q * SKL + k0) * DD;
    int lr = tid >> 3;
    int le = (tid & 7) * 4;

    for (int e0 = 0; e0 < DD; e0 += EC) {
        float4 t4 = *(const float4*)(Tbase + (size_t)lr * DD + e0 + le);
        Ts[lr][le + 0] = t4.x; Ts[lr][le + 1] = t4.y;
        Ts[lr][le + 2] = t4.z; Ts[lr][le + 3] = t4.w;
        float4 p4 = *(const float4*)(Pbase + (size_t)lr * DD + e0 + le);
        Ps[lr][le + 0] = p4.x; Ps[lr][le + 1] = p4.y;
        Ps[lr][le + 2] = p4.z; Ps[lr][le + 3] = p4.w;
        float4 p5 = *(const float4*)(Pbase + (size_t)(lr + 32) * DD + e0 + le);
        Ps[lr + 32][le + 0] = p5.x; Ps[lr + 32][le + 1] = p5.y;
        Ps[lr + 32][le + 2] = p5.z; Ps[lr + 32][le + 3] = p5.w;
        __syncthreads();
        #pragma unroll
        for (int e = 0; e < EC; e++) {
            float a0 = Ts[bg * 2 + 0][e];
            float a1 = Ts[bg * 2 + 1][e];
            #pragma unroll
            for (int j = 0; j < 4; j++) {
                float bv = Ps[kg * 4 + j][e];
                acc0[j] += a0 * bv;
                acc1[j] += a1 * bv;
            }
        }
        __syncthreads();
    }

    #pragma unroll
    for (int i = 0; i < 2; i++) {
        int bh = bg * 2 + i;
        int b = bh >> 3, h = bh & 7;
        float cc = g_c[((size_t)b * SQL + q) * HH + h];
        float* acc = i ? acc1 : acc0;
        float* srow = score + ((size_t)bh * SQL + q) * SKL + k0 + kg * 4;
        float4 sv = *(float4*)srow;
        sv.x = (sv.x + acc[0] + cc) * 0.125f;
        sv.y = (sv.y + acc[1] + cc) * 0.125f;
        sv.z = (sv.z + acc[2] + cc) * 0.125f;
        sv.w = (sv.w + acc[3] + cc) * 0.125f;
        *(float4*)srow = sv;
    }
}

__global__ void softmax_kernel(float* __restrict__ score)
{
    int row = blockIdx.x;
    int q = row & 511;
    int bh = row >> 9;
    int b = bh >> 3;
    int tid = threadIdx.x;         // 128
    float* s = score + (size_t)row * SKL;

    float4 v4 = *(float4*)(s + tid * 4);
    float vals[4] = {v4.x, v4.y, v4.z, v4.w};
    const unsigned char* amr = g_am + (size_t)q * SKL + tid * 4;
    const unsigned char* kpr = g_kpm + (size_t)b * SKL + tid * 4;
    #pragma unroll
    for (int j = 0; j < 4; j++)
        if (amr[j] || kpr[j]) vals[j] = -INFINITY;

    float mx = fmaxf(fmaxf(vals[0], vals[1]), fmaxf(vals[2], vals[3]));
    #pragma unroll
    for (int off = 16; off; off >>= 1)
        mx = fmaxf(mx, __shfl_xor_sync(0xffffffffu, mx, off));
    __shared__ float sm[4], ssum[4];
    int wid = tid >> 5, lane = tid & 31;
    if (lane == 0) sm[wid] = mx;
    __syncthreads();
    mx = fmaxf(fmaxf(sm[0], sm[1]), fmaxf(sm[2], sm[3]));

    float e[4]; float sum = 0.f;
    #pragma unroll
    for (int j = 0; j < 4; j++) {
        e[j] = (vals[j] == -INFINITY) ? 0.f : __expf(vals[j] - mx);
        sum += e[j];
    }
    #pragma unroll
    for (int off = 16; off; off >>= 1)
        sum += __shfl_xor_sync(0xffffffffu, sum, off);
    if (lane == 0) ssum[wid] = sum;
    __syncthreads();
    sum = ssum[0] + ssum[1] + ssum[2] + ssum[3];
    float inv = (sum > 0.f) ? 1.f / sum : 0.f;
    float4 o = {e[0] * inv, e[1] * inv, e[2] * inv, e[3] * inv};
    *(float4*)(s + tid * 4) = o;
}

__global__ void av_kernel(const float* __restrict__ score)
{
    __shared__ float As[16][64];
    __shared__ float Ws[16][64];
    int bh = blockIdx.y, b = bh >> 3, h = bh & 7, hoff = h * DHH;
    int q0 = blockIdx.x * 64;
    int tid = threadIdx.x;
    int tx = tid & 15, ty = tid >> 4;
    float acc[4][4] = {};

    int la_q = tid >> 2, la_k = (tid & 3) * 4;
    int lw_k = tid >> 4, lw_d = (tid & 15) * 4;

    for (int k0 = 0; k0 < SKL; k0 += 16) {
        const unsigned char* rp = g_am + (size_t)(q0 + (tid >> 2)) * SKL + k0 + (tid & 3) * 4;
        int allm = (rp[0] && rp[1] && rp[2] && rp[3]);
        if (__syncthreads_and(allm)) continue;

        float4 a4 = *(const float4*)(score + ((size_t)bh * SQL + q0 + la_q) * SKL + k0 + la_k);
        As[la_k + 0][la_q] = a4.x;
        As[la_k + 1][la_q] = a4.y;
        As[la_k + 2][la_q] = a4.z;
        As[la_k + 3][la_q] = a4.w;
        float4 w4 = *(const float4*)(g_vh + ((size_t)b * SQL + k0 + lw_k) * DD + hoff + lw_d);
        *(float4*)&Ws[lw_k][lw_d] = w4;
        __syncthreads();
        #pragma unroll
        for (int kk = 0; kk < 16; kk++) {
            float a[4], bv[4];
            #pragma unroll
            for (int i = 0; i < 4; i++) a[i] = As[kk][ty * 4 + i];
            #pragma unroll
            for (int j = 0; j < 4; j++) bv[j] = Ws[kk][tx * 4 + j];
            #pragma unroll
            for (int i = 0; i < 4; i++)
                #pragma unroll
                for (int j = 0; j < 4; j++)
                    acc[i][j] += a[i] * bv[j];
        }
        __syncthreads();
    }
    #pragma unroll
    for (int i = 0; i < 4; i++) {
        float4 sv = {acc[i][0], acc[i][1], acc[i][2], acc[i][3]};
        *(float4*)(g_att + ((size_t)b * SQL + q0 + ty * 4 + i) * DD + hoff + tx * 4) = sv;
    }
}

__global__ void ln_kernel(const float* __restrict__ X, const float* __restrict__ gamma,
                          const float* __restrict__ beta, float* __restrict__ out)
{
    int row = blockIdx.x;
    int tid = threadIdx.x;  // 256
    const float* x = X + (size_t)row * DD;
    float2 v = *(const float2*)(x + tid * 2);
    float s = v.x + v.y;
    float s2 = v.x * v.x + v.y * v.y;
    #pragma unroll
    for (int off = 16; off; off >>= 1) {
        s  += __shfl_xor_sync(0xffffffffu, s, off);
        s2 += __shfl_xor_sync(0xffffffffu, s2, off);
    }
    __shared__ float rs[8], rs2[8];
    int wid = tid >> 5, lane = tid & 31;
    if (lane == 0) { rs[wid] = s; rs2[wid] = s2; }
    __syncthreads();
    s = 0.f; s2 = 0.f;
    #pragma unroll
    for (int i = 0; i < 8; i++) { s += rs[i]; s2 += rs2[i]; }
    float mean = s * (1.f / DD);
    float var = s2 * (1.f / DD) - mean * mean;
    float inv = rsqrtf(var + 1e-5f);
    float2 g2 = *(const float2*)(gamma + tid * 2);
    float2 b2 = *(const float2*)(beta + tid * 2);
    float2 o;
    o.x = (v.x - mean) * inv * g2.x + b2.x;
    o.y = (v.y - mean) * inv * g2.y + b2.y;
    *(float2*)(out + (size_t)row * DD + tid * 2) = o;
}

// ===========================================================================
extern "C" void kernel_launch(void* const* d_in, const int* in_sizes, int n_in,
                              void* d_out, int out_size)
{
    const float* q  = (const float*)d_in[0];
    const float* k  = (const float*)d_in[1];
    const float* v  = (const float*)d_in[2];
    const float* pe = (const float*)d_in[3];
    const unsigned char* kpm = (const unsigned char*)d_in[4];
    const unsigned char* am  = (const unsigned char*)d_in[5];
    const float* Wq = (const float*)d_in[6];
    const float* bq = (const float*)d_in[7];
    const float* Wk = (const float*)d_in[8];
    const float* bk = (const float*)d_in[9];
    const float* Wv = (const float*)d_in[10];
    const float* bv = (const float*)d_in[11];
    const float* Wo = (const float*)d_in[12];
    const float* bo = (const float*)d_in[13];
    const float* Wr = (const float*)d_in[14];
    const float* br = (const float*)d_in[15];
    const float* ub = (const float*)d_in[16];
    const float* vb = (const float*)d_in[17];
    const float* lg = (const float*)d_in[18];
    const float* lb = (const float*)d_in[19];

    float* normed = (float*)d_out;
    float* attnw  = normed + (size_t)BB * SQL * DD;

    float *qh, *kh, *vh, *att, *o2;
    cudaGetSymbolAddress((void**)&qh,  g_qh);
    cudaGetSymbolAddress((void**)&kh,  g_kh);
    cudaGetSymbolAddress((void**)&vh,  g_vh);
    cudaGetSymbolAddress((void**)&att, g_att);
    cudaGetSymbolAddress((void**)&o2,  g_o2);

    mask_detect<<<1, 1024>>>(am);
    mask_convert<<<64, 256>>>(am, kpm);

    mma_gemm<<<dim3(8, 16), 256>>>(q, Wq, bq, nullptr, qh);
    mma_gemm<<<dim3(8, 16), 256>>>(k, Wk, bk, nullptr, kh);
    mma_gemm<<<dim3(8, 16), 256>>>(v, Wv, bv, nullptr, vh);

    c_kernel<<<(MR * HH + 255) / 256, 256>>>(vb, br);
    t_kernel<<<dim3(8, 32, 8), 256>>>(Wr, vb);

    ac_kernel<<<dim3(8, 8, 32), 256>>>(ub, attnw);
    bd_kernel<<<dim3(8, 512), 256>>>(pe, attnw);
    softmax_kernel<<<BHH * SQL, 128>>>(attnw);

    av_kernel<<<dim3(8, 32), 256>>>(attnw);

    mma_gemm<<<dim3(8, 16), 256>>>(att, Wo, bo, q, o2);
    ln_kernel<<<MR, 256>>>(o2, lg, lb, normed);
}

// round 8
// speedup vs baseline: 2.0503x; 1.5156x over previous
#include <cuda_runtime.h>
#include <cuda_bf16.h>
#include <math.h>
#include <stdint.h>

#define BB   4
#define SQL  512
#define SKL  512
#define DD   512
#define HH   8
#define DHH  64
#define BHH  32
#define MR   2048

// ---------------- f32 scratch ----------------
__device__ float g_qh[MR * DD];
__device__ float g_kh[MR * DD];
__device__ float g_vh[MR * DD];
__device__ float g_c [MR * HH];
__device__ float g_att[MR * DD];
__device__ float g_o2 [MR * DD];

// ---------------- bf16 hi/lo scratch ----------------
__device__ __nv_bfloat16 g_qi_h[MR * DD], g_qi_l[MR * DD];
__device__ __nv_bfloat16 g_ki_h[MR * DD], g_ki_l[MR * DD];
__device__ __nv_bfloat16 g_vi_h[MR * DD], g_vi_l[MR * DD];
__device__ __nv_bfloat16 g_wq_h[DD * DD], g_wq_l[DD * DD];
__device__ __nv_bfloat16 g_wk_h[DD * DD], g_wk_l[DD * DD];
__device__ __nv_bfloat16 g_wv_h[DD * DD], g_wv_l[DD * DD];
__device__ __nv_bfloat16 g_wo_h[DD * DD], g_wo_l[DD * DD];
__device__ __nv_bfloat16 g_wr_h[DD * DD], g_wr_l[DD * DD];
__device__ __nv_bfloat16 g_qv_h[MR * DD], g_qv_l[MR * DD];   // split(qh + v_bias)
__device__ __nv_bfloat16 g_T_h[SQL * BHH * DD], g_T_l[SQL * BHH * DD]; // [q][bh][e]
__device__ __nv_bfloat16 g_at_h[MR * DD], g_at_l[MR * DD];

__device__ unsigned char g_am [SQL * SKL];
__device__ unsigned char g_kpm[BB * SKL];
__device__ unsigned int g_or1, g_or23;

// ===========================================================================
// helpers
// ===========================================================================
__device__ __forceinline__ uint32_t smem_u32(const void* p) {
    uint32_t a;
    asm("{ .reg .u64 t; cvta.to.shared.u64 t, %1; cvt.u32.u64 %0, t; }" : "=r"(a) : "l"(p));
    return a;
}
__device__ __forceinline__ uint32_t pack_bf16x2(float x, float y) {
    uint32_t r;
    asm("cvt.rn.bf16x2.f32 %0, %1, %2;" : "=r"(r) : "f"(y), "f"(x));
    return r;   // low 16 bits = x, high = y (memory order: x, y)
}
__device__ __forceinline__ float bf_lo(uint32_t w) { return __uint_as_float(w << 16); }
__device__ __forceinline__ float bf_hi(uint32_t w) { return __uint_as_float(w & 0xffff0000u); }

#define MMA_BF16(c, a, b0, b1) \
    asm volatile("mma.sync.aligned.m16n8k16.row.col.f32.bf16.bf16.f32 " \
        "{%0,%1,%2,%3}, {%4,%5,%6,%7}, {%8,%9}, {%0,%1,%2,%3};" \
        : "+f"((c)[0]), "+f"((c)[1]), "+f"((c)[2]), "+f"((c)[3]) \
        : "r"((a)[0]), "r"((a)[1]), "r"((a)[2]), "r"((a)[3]), "r"(b0), "r"(b1))

__device__ __forceinline__ void cpa16(const void* s, const void* g) {
    asm volatile("cp.async.ca.shared.global [%0], [%1], 16;" :: "r"(smem_u32(s)), "l"(g));
}
// split 2 floats -> hi u32 + lo u32 (bf16x2 each)
__device__ __forceinline__ void split2(float x, float y, uint32_t& h, uint32_t& l) {
    h = pack_bf16x2(x, y);
    l = pack_bf16x2(x - bf_lo(h), y - bf_hi(h));
}

// ===========================================================================
// Conversion kernels
// ===========================================================================
__global__ void conv_inputs(const float* __restrict__ q, const float* __restrict__ k,
                            const float* __restrict__ v)
{
    const float* src = (blockIdx.z == 0) ? q : (blockIdx.z == 1) ? k : v;
    __nv_bfloat16* dh = (blockIdx.z == 0) ? g_qi_h : (blockIdx.z == 1) ? g_ki_h : g_vi_h;
    __nv_bfloat16* dl = (blockIdx.z == 0) ? g_qi_l : (blockIdx.z == 1) ? g_ki_l : g_vi_l;
    int idx = (blockIdx.x * blockDim.x + threadIdx.x) * 4;
    if (idx >= MR * DD) return;
    float4 a = *(const float4*)(src + idx);
    uint32_t h0, l0, h1, l1;
    split2(a.x, a.y, h0, l0);
    split2(a.z, a.w, h1, l1);
    *(uint2*)((uint16_t*)dh + idx) = make_uint2(h0, h1);
    *(uint2*)((uint16_t*)dl + idx) = make_uint2(l0, l1);
}

// W[k][n] -> out[n][k] hi/lo (transpose)
__global__ void conv_w(const float* __restrict__ Wq, const float* __restrict__ Wk,
                       const float* __restrict__ Wv, const float* __restrict__ Wo)
{
    __shared__ float s[32][33];
    const float* W = (blockIdx.z == 0) ? Wq : (blockIdx.z == 1) ? Wk : (blockIdx.z == 2) ? Wv : Wo;
    __nv_bfloat16* dh = (blockIdx.z == 0) ? g_wq_h : (blockIdx.z == 1) ? g_wk_h : (blockIdx.z == 2) ? g_wv_h : g_wo_h;
    __nv_bfloat16* dl = (blockIdx.z == 0) ? g_wq_l : (blockIdx.z == 1) ? g_wk_l : (blockIdx.z == 2) ? g_wv_l : g_wo_l;
    int k0 = blockIdx.y * 32, n0 = blockIdx.x * 32;
    int tx = threadIdx.x, ty = threadIdx.y;
    s[ty][tx] = W[(size_t)(k0 + ty) * DD + n0 + tx];
    __syncthreads();
    float vv = s[tx][ty];   // = W[k0+tx][n0+ty]
    __nv_bfloat16 hb = __float2bfloat16_rn(vv);
    __nv_bfloat16 lb = __float2bfloat16_rn(vv - __bfloat162float(hb));
    dh[(size_t)(n0 + ty) * DD + k0 + tx] = hb;
    dl[(size_t)(n0 + ty) * DD + k0 + tx] = lb;
}

__global__ void conv_wr(const float* __restrict__ Wr)
{
    int idx = (blockIdx.x * blockDim.x + threadIdx.x) * 4;
    if (idx >= DD * DD) return;
    float4 a = *(const float4*)(Wr + idx);
    uint32_t h0, l0, h1, l1;
    split2(a.x, a.y, h0, l0);
    split2(a.z, a.w, h1, l1);
    *(uint2*)((uint16_t*)g_wr_h + idx) = make_uint2(h0, h1);
    *(uint2*)((uint16_t*)g_wr_l + idx) = make_uint2(l0, l1);
}

// ===========================================================================
// Mask normalization
// ===========================================================================
__global__ void zero_flags() { g_or1 = 0; g_or23 = 0; }

__global__ void mask_detect(const unsigned char* __restrict__ am)
{
    unsigned int or1 = 0, or23 = 0;
    const uint4* p = (const uint4*)am;
    int n16 = SQL * SKL / 16;
    for (int i = blockIdx.x * blockDim.x + threadIdx.x; i < n16; i += gridDim.x * blockDim.x) {
        uint4 v = p[i];
        or1  |= (v.x & 0x0000FF00u) | (v.y & 0x0000FF00u) | (v.z & 0x0000FF00u) | (v.w & 0x0000FF00u);
        or23 |= (v.x & 0xFFFF0000u) | (v.y & 0xFFFF0000u) | (v.z & 0xFFFF0000u) | (v.w & 0xFFFF0000u);
    }
    int a1 = __syncthreads_or((int)(or1 != 0));
    int a23 = __syncthreads_or((int)(or23 != 0));
    if (threadIdx.x == 0) {
        if (a1) atomicOr(&g_or1, 1u);
        if (a23) atomicOr(&g_or23, 1u);
    }
}

__global__ void mask_convert(const unsigned char* __restrict__ am,
                             const unsigned char* __restrict__ kpm)
{
    int mode = g_or1 ? 1 : (g_or23 ? 2 : 0);
    int stride = gridDim.x * blockDim.x;
    int tid = blockIdx.x * blockDim.x + threadIdx.x;
    for (int i = tid; i < SQL * SKL; i += stride) {
        unsigned char v;
        if (mode == 1)      v = (am[i] != 0);
        else if (mode == 2) v = (((const float*)am)[i] != 0.0f);
        else                v = (((const int*)am)[i] != 0);
        g_am[i] = v;
    }
    for (int i = tid; i < BB * SKL; i += stride) {
        unsigned char v;
        if (mode == 1)      v = (kpm[i] != 0);
        else if (mode == 2) v = (((const float*)kpm)[i] != 0.0f);
        else                v = (((const int*)kpm)[i] != 0);
        g_kpm[i] = v;
    }
}

// ===========================================================================
// mma2: C[2048,512] = A @ W + bias (+resid), pre-converted bf16 hi/lo operands.
// BM=64 BN=64 BK=32, cp.async double buffer, 256 thr (8 warps 2x4).
// Optional: o2 = split(C + rowbias) hi/lo.
// ===========================================================================
__global__ void __launch_bounds__(256, 2)
mma2(const __nv_bfloat16* __restrict__ Ahg, const __nv_bfloat16* __restrict__ Alg,
     const __nv_bfloat16* __restrict__ Bhg, const __nv_bfloat16* __restrict__ Blg,
     const float* __restrict__ bias, const float* __restrict__ resid,
     float* __restrict__ C,
     __nv_bfloat16* __restrict__ o2h, __nv_bfloat16* __restrict__ o2l,
     const float* __restrict__ rowbias)
{
    __shared__ __align__(16) __nv_bfloat16 sA[2][2][64][40];
    __shared__ __align__(16) __nv_bfloat16 sB[2][2][64][40];
    int tid = threadIdx.x, lane = tid & 31, wid = tid >> 5;
    int wm = wid >> 2, wn = wid & 3;
    int row0 = blockIdx.y * 64, n0 = blockIdx.x * 64;
    int r = lane >> 2, t4 = lane & 3;
    float acc[2][2][4] = {};
    int lrow = tid >> 2, lco = (tid & 3) * 8;

    // prologue: stage 0
    {
        int k0 = 0;
        cpa16(&sA[0][0][lrow][lco], (const uint16_t*)Ahg + (size_t)(row0 + lrow) * DD + k0 + lco);
        cpa16(&sA[0][1][lrow][lco], (const uint16_t*)Alg + (size_t)(row0 + lrow) * DD + k0 + lco);
        cpa16(&sB[0][0][lrow][lco], (const uint16_t*)Bhg + (size_t)(n0 + lrow) * DD + k0 + lco);
        cpa16(&sB[0][1][lrow][lco], (const uint16_t*)Blg + (size_t)(n0 + lrow) * DD + k0 + lco);
        asm volatile("cp.async.commit_group;");
    }
    #pragma unroll 1
    for (int it = 0; it < 16; it++) {
        if (it + 1 < 16) {
            int st = (it + 1) & 1, k0 = (it + 1) * 32;
            cpa16(&sA[st][0][lrow][lco], (const uint16_t*)Ahg + (size_t)(row0 + lrow) * DD + k0 + lco);
            cpa16(&sA[st][1][lrow][lco], (const uint16_t*)Alg + (size_t)(row0 + lrow) * DD + k0 + lco);
            cpa16(&sB[st][0][lrow][lco], (const uint16_t*)Bhg + (size_t)(n0 + lrow) * DD + k0 + lco);
            cpa16(&sB[st][1][lrow][lco], (const uint16_t*)Blg + (size_t)(n0 + lrow) * DD + k0 + lco);
            asm volatile("cp.async.commit_group;");
            asm volatile("cp.async.wait_group 1;");
        } else {
            asm volatile("cp.async.wait_group 0;");
        }
        __syncthreads();
        int st = it & 1;
        #pragma unroll
        for (int ks = 0; ks < 2; ks++) {
            uint32_t ah[2][4], al[2][4];
            #pragma unroll
            for (int mi = 0; mi < 2; mi++) {
                int row = wm * 32 + mi * 16 + r;
                const __nv_bfloat16* ph = &sA[st][0][row][ks * 16 + t4 * 2];
                const __nv_bfloat16* pl = &sA[st][1][row][ks * 16 + t4 * 2];
                ah[mi][0] = *(const uint32_t*)ph;
                ah[mi][1] = *(const uint32_t*)(ph + 8 * 40);
                ah[mi][2] = *(const uint32_t*)(ph + 8);
                ah[mi][3] = *(const uint32_t*)(ph + 8 * 40 + 8);
                al[mi][0] = *(const uint32_t*)pl;
                al[mi][1] = *(const uint32_t*)(pl + 8 * 40);
                al[mi][2] = *(const uint32_t*)(pl + 8);
                al[mi][3] = *(const uint32_t*)(pl + 8 * 40 + 8);
            }
            #pragma unroll
            for (int nj = 0; nj < 2; nj++) {
                int n = wn * 16 + nj * 8 + r;
                const __nv_bfloat16* qh = &sB[st][0][n][ks * 16 + t4 * 2];
                const __nv_bfloat16* ql = &sB[st][1][n][ks * 16 + t4 * 2];
                uint32_t bh0 = *(const uint32_t*)qh, bh1 = *(const uint32_t*)(qh + 8);
                uint32_t bl0 = *(const uint32_t*)ql, bl1 = *(const uint32_t*)(ql + 8);
                #pragma unroll
                for (int mi = 0; mi < 2; mi++) {
                    MMA_BF16(acc[mi][nj], ah[mi], bh0, bh1);
                    MMA_BF16(acc[mi][nj], ah[mi], bl0, bl1);
                    MMA_BF16(acc[mi][nj], al[mi], bh0, bh1);
                }
            }
        }
        __syncthreads();
    }
    // epilogue
    #pragma unroll
    for (int mi = 0; mi < 2; mi++) {
        #pragma unroll
        for (int nj = 0; nj < 2; nj++) {
            int col = n0 + wn * 16 + nj * 8 + t4 * 2;
            float b0 = bias[col], b1 = bias[col + 1];
            float rb0 = rowbias ? rowbias[col] : 0.f;
            float rb1 = rowbias ? rowbias[col + 1] : 0.f;
            #pragma unroll
            for (int rr = 0; rr < 2; rr++) {
                int row = row0 + wm * 32 + mi * 16 + r + rr * 8;
                float v0 = acc[mi][nj][rr * 2 + 0] + b0;
                float v1 = acc[mi][nj][rr * 2 + 1] + b1;
                if (resid) {
                    float2 r2 = *(const float2*)(resid + (size_t)row * DD + col);
                    v0 += r2.x; v1 += r2.y;
                }
                *(float2*)(C + (size_t)row * DD + col) = make_float2(v0, v1);
                if (o2h) {
                    uint32_t h, l;
                    split2(v0 + rb0, v1 + rb1, h, l);
                    *(uint32_t*)((uint16_t*)o2h + (size_t)row * DD + col) = h;
                    *(uint32_t*)((uint16_t*)o2l + (size_t)row * DD + col) = l;
                }
            }
        }
    }
}

// ===========================================================================
// t_mma: T[q][bh][e] (hi/lo) = (qh + v_bias) @ Wr_h^T,  per head.
// BM=64(m) BN=64(e) K=64. grid (8 e, 32 m, 8 h), 256 thr.
// ===========================================================================
__global__ void __launch_bounds__(256, 2)
t_mma()
{
    __shared__ __align__(16) __nv_bfloat16 tA[2][64][72];  // [hi/lo][m][d]
    __shared__ __align__(16) __nv_bfloat16 tB[2][64][72];  // [hi/lo][e][d]
    int tid = threadIdx.x, lane = tid & 31, wid = tid >> 5;
    int wm = wid >> 2, wn = wid & 3;
    int h = blockIdx.z, hoff = h * DHH;
    int m0 = blockIdx.y * 64, e0 = blockIdx.x * 64;
    int r = lane >> 2, t4 = lane & 3;
    float acc[2][2][4] = {};

    // load tiles: each array 64 rows x 64 elems; 512 chunks of 16B; 2/thread/array
    #pragma unroll
    for (int j = 0; j < 2; j++) {
        int c = tid + j * 256;
        int row = c >> 3, off = (c & 7) * 8;
        *(uint4*)&tA[0][row][off] = *(const uint4*)((const uint16_t*)g_qv_h + (size_t)(m0 + row) * DD + hoff + off);
        *(uint4*)&tA[1][row][off] = *(const uint4*)((const uint16_t*)g_qv_l + (size_t)(m0 + row) * DD + hoff + off);
        *(uint4*)&tB[0][row][off] = *(const uint4*)((const uint16_t*)g_wr_h + (size_t)(e0 + row) * DD + hoff + off);
        *(uint4*)&tB[1][row][off] = *(const uint4*)((const uint16_t*)g_wr_l + (size_t)(e0 + row) * DD + hoff + off);
    }
    __syncthreads();

    #pragma unroll
    for (int ks = 0; ks < 4; ks++) {
        uint32_t ah[2][4], al[2][4];
        #pragma unroll
        for (int mi = 0; mi < 2; mi++) {
            int row = wm * 32 + mi * 16 + r;
            const __nv_bfloat16* ph = &tA[0][row][ks * 16 + t4 * 2];
            const __nv_bfloat16* pl = &tA[1][row][ks * 16 + t4 * 2];
            ah[mi][0] = *(const uint32_t*)ph;
            ah[mi][1] = *(const uint32_t*)(ph + 8 * 72);
            ah[mi][2] = *(const uint32_t*)(ph + 8);
            ah[mi][3] = *(const uint32_t*)(ph + 8 * 72 + 8);
            al[mi][0] = *(const uint32_t*)pl;
            al[mi][1] = *(const uint32_t*)(pl + 8 * 72);
            al[mi][2] = *(const uint32_t*)(pl + 8);
            al[mi][3] = *(const uint32_t*)(pl + 8 * 72 + 8);
        }
        #pragma unroll
        for (int nj = 0; nj < 2; nj++) {
            int n = wn * 16 + nj * 8 + r;
            const __nv_bfloat16* qh = &tB[0][n][ks * 16 + t4 * 2];
            const __nv_bfloat16* ql = &tB[1][n][ks * 16 + t4 * 2];
            uint32_t bh0 = *(const uint32_t*)qh, bh1 = *(const uint32_t*)(qh + 8);
            uint32_t bl0 = *(const uint32_t*)ql, bl1 = *(const uint32_t*)(ql + 8);
            #pragma unroll
            for (int mi = 0; mi < 2; mi++) {
                MMA_BF16(acc[mi][nj], ah[mi], bh0, bh1);
                MMA_BF16(acc[mi][nj], ah[mi], bl0, bl1);
                MMA_BF16(acc[mi][nj], al[mi], bh0, bh1);
            }
        }
    }
    // epilogue: write hi/lo T at [q][bh][e]
    #pragma unroll
    for (int mi = 0; mi < 2; mi++) {
        #pragma unroll
        for (int nj = 0; nj < 2; nj++) {
            int e = e0 + wn * 16 + nj * 8 + t4 * 2;
            #pragma unroll
            for (int rr = 0; rr < 2; rr++) {
                int m = m0 + wm * 32 + mi * 16 + r + rr * 8;
                int q = m & 511, b = m >> 9;
                int bh = b * HH + h;
                uint32_t hh, ll;
                split2(acc[mi][nj][rr * 2 + 0], acc[mi][nj][rr * 2 + 1], hh, ll);
                size_t di = ((size_t)q * BHH + bh) * DD + e;
                *(uint32_t*)((uint16_t*)g_T_h + di) = hh;
                *(uint32_t*)((uint16_t*)g_T_l + di) = ll;
            }
        }
    }
}

// c[b,q,h] = sum_d (qh+v_bias)*br_h
__global__ void c_kernel(const float* __restrict__ vb, const float* __restrict__ br)
{
    int idx = blockIdx.x * blockDim.x + threadIdx.x;
    if (idx >= MR * HH) return;
    int h = idx & 7;
    int m = idx >> 3;
    int hoff = h * DHH;
    const float* qrow = g_qh + (size_t)m * DD + hoff;
    float s = 0.f;
    #pragma unroll 8
    for (int d = 0; d < DHH; d++)
        s += (qrow[d] + vb[hoff + d]) * br[hoff + d];
    g_c[idx] = s;
}

// ===========================================================================
// ac (scalar, R2): score[bh,q,k] = sum_d (qh+u)*kh
// ===========================================================================
__global__ void ac_kernel(const float* __restrict__ ub, float* __restrict__ score)
{
    __shared__ float As[16][64];
    __shared__ float Ks[16][64];
    int bh = blockIdx.z, b = bh >> 3, h = bh & 7, hoff = h * DHH;
    int q0 = blockIdx.y * 64, k0 = blockIdx.x * 64;
    int tid = threadIdx.x;
    int tx = tid & 15, ty = tid >> 4;

    const unsigned char* rp = g_am + (size_t)(q0 + (tid >> 2)) * SKL + k0 + (tid & 3) * 16;
    int allm = 1;
    #pragma unroll
    for (int j = 0; j < 16; j++) allm &= (rp[j] != 0);
    if (__syncthreads_and(allm)) return;

    int lr = tid >> 2, lc = (tid & 3) * 4;
    float acc[4][4] = {};
    for (int d0 = 0; d0 < DHH; d0 += 16) {
        float4 a4 = *(const float4*)(g_qh + ((size_t)b * SQL + q0 + lr) * DD + hoff + d0 + lc);
        float4 u4 = *(const float4*)(ub + hoff + d0 + lc);
        As[lc + 0][lr] = a4.x + u4.x;
        As[lc + 1][lr] = a4.y + u4.y;
        As[lc + 2][lr] = a4.z + u4.z;
        As[lc + 3][lr] = a4.w + u4.w;
        float4 k4 = *(const float4*)(g_kh + ((size_t)b * SQL + k0 + lr) * DD + hoff + d0 + lc);
        Ks[lc + 0][lr] = k4.x;
        Ks[lc + 1][lr] = k4.y;
        Ks[lc + 2][lr] = k4.z;
        Ks[lc + 3][lr] = k4.w;
        __syncthreads();
        #pragma unroll
        for (int kk = 0; kk < 16; kk++) {
            float a[4], bv[4];
            #pragma unroll
            for (int i = 0; i < 4; i++) a[i] = As[kk][ty * 4 + i];
            #pragma unroll
            for (int j = 0; j < 4; j++) bv[j] = Ks[kk][tx * 4 + j];
            #pragma unroll
            for (int i = 0; i < 4; i++)
                #pragma unroll
                for (int j = 0; j < 4; j++)
                    acc[i][j] += a[i] * bv[j];
        }
        __syncthreads();
    }
    #pragma unroll
    for (int i = 0; i < 4; i++) {
        float4 sv = {acc[i][0], acc[i][1], acc[i][2], acc[i][3]};
        *(float4*)(score + ((size_t)bh * SQL + q0 + ty * 4 + i) * SKL + k0 + tx * 4) = sv;
    }
}

// ===========================================================================
// bd_mma: score[bh,q,k] = (ac + T[q,bh,:]@pos_emb[q,k,:] + c)/8 via mma.
// One block per q. M=32(bh), N=512(k) split over 8 warps, K=512(e).
// T staged hi/lo in smem; pos_emb fragments straight from gmem, split on fly.
// ===========================================================================
__global__ void __launch_bounds__(256)
bd_mma(const float* __restrict__ pos_emb, float* __restrict__ score)
{
    __shared__ __align__(16) __nv_bfloat16 sT[2][32][136];  // [hi/lo][bh][e-chunk 128]
    int q = blockIdx.x;
    int tid = threadIdx.x, lane = tid & 31, wn = tid >> 5;
    int r = lane >> 2, t4 = lane & 3;

    // causal/warp activity: warp wn covers k in [wn*64, wn*64+64)
    int k_a = wn * 64 + lane * 2;
    unsigned char ma = g_am[(size_t)q * SKL + k_a];
    unsigned char mb = g_am[(size_t)q * SKL + k_a + 1];
    int act = __ballot_sync(0xffffffffu, (ma == 0) || (mb == 0)) != 0;

    float acc[2][8][4] = {};

    #pragma unroll 1
    for (int ec = 0; ec < 4; ec++) {
        // stage T chunk: 2 arrays x 32 rows x 128 elems; 512 chunks of 16B
        #pragma unroll
        for (int j = 0; j < 2; j++) {
            int c = tid + j * 256;
            int row = c >> 4, off = (c & 15) * 8;
            size_t gi = ((size_t)q * BHH + row) * DD + ec * 128 + off;
            *(uint4*)&sT[0][row][off] = *(const uint4*)((const uint16_t*)g_T_h + gi);
            *(uint4*)&sT[1][row][off] = *(const uint4*)((const uint16_t*)g_T_l + gi);
        }
        __syncthreads();
        if (act) {
            #pragma unroll 1
            for (int ks = 0; ks < 8; ks++) {
                uint32_t ah[2][4], al[2][4];
                #pragma unroll
                for (int mi = 0; mi < 2; mi++) {
                    int row = mi * 16 + r;
                    const __nv_bfloat16* ph = &sT[0][row][ks * 16 + t4 * 2];
                    const __nv_bfloat16* pl = &sT[1][row][ks * 16 + t4 * 2];
                    ah[mi][0] = *(const uint32_t*)ph;
                    ah[mi][1] = *(const uint32_t*)(ph + 8 * 136);
                    ah[mi][2] = *(const uint32_t*)(ph + 8);
                    ah[mi][3] = *(const uint32_t*)(ph + 8 * 136 + 8);
                    al[mi][0] = *(const uint32_t*)pl;
                    al[mi][1] = *(const uint32_t*)(pl + 8 * 136);
                    al[mi][2] = *(const uint32_t*)(pl + 8);
                    al[mi][3] = *(const uint32_t*)(pl + 8 * 136 + 8);
                }
                int eg = ec * 128 + ks * 16 + t4 * 2;
                #pragma unroll
                for (int nj = 0; nj < 8; nj++) {
                    int n = wn * 64 + nj * 8 + r;
                    const float* pp = pos_emb + ((size_t)q * SKL + n) * DD + eg;
                    float2 p0 = *(const float2*)pp;
                    float2 p1 = *(const float2*)(pp + 8);
                    uint32_t bh0, bl0, bh1, bl1;
                    split2(p0.x, p0.y, bh0, bl0);
                    split2(p1.x, p1.y, bh1, bl1);
                    #pragma unroll
                    for (int mi = 0; mi < 2; mi++) {
                        MMA_BF16(acc[mi][nj], ah[mi], bh0, bh1);
                        MMA_BF16(acc[mi][nj], ah[mi], bl0, bl1);
                        MMA_BF16(acc[mi][nj], al[mi], bh0, bh1);
                    }
                }
            }
        }
        __syncthreads();
    }
    if (!act) return;
    // epilogue: score = (ac + bd + c)/8
    #pragma unroll
    for (int mi = 0; mi < 2; mi++) {
        #pragma unroll
        for (int rr = 0; rr < 2; rr++) {
            int bh = mi * 16 + r + rr * 8;
            int b = bh >> 3, h = bh & 7;
            float cc = g_c[((size_t)b * SQL + q) * HH + h];
            float* srow = score + ((size_t)bh * SQL + q) * SKL;
            #pragma unroll
            for (int nj = 0; nj < 8; nj++) {
                int k = wn * 64 + nj * 8 + t4 * 2;
                float2 s2 = *(float2*)(srow + k);
                s2.x = (s2.x + acc[mi][nj][rr * 2 + 0] + cc) * 0.125f;
                s2.y = (s2.y + acc[mi][nj][rr * 2 + 1] + cc) * 0.125f;
                *(float2*)(srow + k) = s2;
            }
        }
    }
}

// ===========================================================================
__global__ void softmax_kernel(float* __restrict__ score)
{
    int row = blockIdx.x;
    int q = row & 511;
    int bh = row >> 9;
    int b = bh >> 3;
    int tid = threadIdx.x;         // 128
    float* s = score + (size_t)row * SKL;

    float4 v4 = *(float4*)(s + tid * 4);
    float vals[4] = {v4.x, v4.y, v4.z, v4.w};
    const unsigned char* amr = g_am + (size_t)q * SKL + tid * 4;
    const unsigned char* kpr = g_kpm + (size_t)b * SKL + tid * 4;
    #pragma unroll
    for (int j = 0; j < 4; j++)
        if (amr[j] || kpr[j]) vals[j] = -INFINITY;

    float mx = fmaxf(fmaxf(vals[0], vals[1]), fmaxf(vals[2], vals[3]));
    #pragma unroll
    for (int off = 16; off; off >>= 1)
        mx = fmaxf(mx, __shfl_xor_sync(0xffffffffu, mx, off));
    __shared__ float sm[4], ssum[4];
    int wid = tid >> 5, lane = tid & 31;
    if (lane == 0) sm[wid] = mx;
    __syncthreads();
    mx = fmaxf(fmaxf(sm[0], sm[1]), fmaxf(sm[2], sm[3]));

    float e[4]; float sum = 0.f;
    #pragma unroll
    for (int j = 0; j < 4; j++) {
        e[j] = (vals[j] == -INFINITY) ? 0.f : __expf(vals[j] - mx);
        sum += e[j];
    }
    #pragma unroll
    for (int off = 16; off; off >>= 1)
        sum += __shfl_xor_sync(0xffffffffu, sum, off);
    if (lane == 0) ssum[wid] = sum;
    __syncthreads();
    sum = ssum[0] + ssum[1] + ssum[2] + ssum[3];
    float inv = (sum > 0.f) ? 1.f / sum : 0.f;
    float4 o = {e[0] * inv, e[1] * inv, e[2] * inv, e[3] * inv};
    *(float4*)(s + tid * 4) = o;
}

// ===========================================================================
// av (scalar R2) + fused hi/lo split of the output
// ===========================================================================
__global__ void av_kernel(const float* __restrict__ score)
{
    __shared__ float As[16][64];
    __shared__ float Ws[16][64];
    int bh = blockIdx.y, b = bh >> 3, h = bh & 7, hoff = h * DHH;
    int q0 = blockIdx.x * 64;
    int tid = threadIdx.x;
    int tx = tid & 15, ty = tid >> 4;
    float acc[4][4] = {};

    int la_q = tid >> 2, la_k = (tid & 3) * 4;
    int lw_k = tid >> 4, lw_d = (tid & 15) * 4;

    for (int k0 = 0; k0 < SKL; k0 += 16) {
        const unsigned char* rp = g_am + (size_t)(q0 + (tid >> 2)) * SKL + k0 + (tid & 3) * 4;
        int allm = (rp[0] && rp[1] && rp[2] && rp[3]);
        if (__syncthreads_and(allm)) continue;

        float4 a4 = *(const float4*)(score + ((size_t)bh * SQL + q0 + la_q) * SKL + k0 + la_k);
        As[la_k + 0][la_q] = a4.x;
        As[la_k + 1][la_q] = a4.y;
        As[la_k + 2][la_q] = a4.z;
        As[la_k + 3][la_q] = a4.w;
        float4 w4 = *(const float4*)(g_vh + ((size_t)b * SQL + k0 + lw_k) * DD + hoff + lw_d);
        *(float4*)&Ws[lw_k][lw_d] = w4;
        __syncthreads();
        #pragma unroll
        for (int kk = 0; kk < 16; kk++) {
            float a[4], bv[4];
            #pragma unroll
            for (int i = 0; i < 4; i++) a[i] = As[kk][ty * 4 + i];
            #pragma unroll
            for (int j = 0; j < 4; j++) bv[j] = Ws[kk][tx * 4 + j];
            #pragma unroll
            for (int i = 0; i < 4; i++)
                #pragma unroll
                for (int j = 0; j < 4; j++)
                    acc[i][j] += a[i] * bv[j];
        }
        __syncthreads();
    }
    #pragma unroll
    for (int i = 0; i < 4; i++) {
        size_t oi = ((size_t)b * SQL + q0 + ty * 4 + i) * DD + hoff + tx * 4;
        float4 sv = {acc[i][0], acc[i][1], acc[i][2], acc[i][3]};
        *(float4*)(g_att + oi) = sv;
        uint32_t h0, l0, h1, l1;
        split2(sv.x, sv.y, h0, l0);
        split2(sv.z, sv.w, h1, l1);
        *(uint2*)((uint16_t*)g_at_h + oi) = make_uint2(h0, h1);
        *(uint2*)((uint16_t*)g_at_l + oi) = make_uint2(l0, l1);
    }
}

// ===========================================================================
__global__ void ln_kernel(const float* __restrict__ X, const float* __restrict__ gamma,
                          const float* __restrict__ beta, float* __restrict__ out)
{
    int row = blockIdx.x;
    int tid = threadIdx.x;  // 256
    const float* x = X + (size_t)row * DD;
    float2 v = *(const float2*)(x + tid * 2);
    float s = v.x + v.y;
    float s2 = v.x * v.x + v.y * v.y;
    #pragma unroll
    for (int off = 16; off; off >>= 1) {
        s  += __shfl_xor_sync(0xffffffffu, s, off);
        s2 += __shfl_xor_sync(0xffffffffu, s2, off);
    }
    __shared__ float rs[8], rs2[8];
    int wid = tid >> 5, lane = tid & 31;
    if (lane == 0) { rs[wid] = s; rs2[wid] = s2; }
    __syncthreads();
    s = 0.f; s2 = 0.f;
    #pragma unroll
    for (int i = 0; i < 8; i++) { s += rs[i]; s2 += rs2[i]; }
    float mean = s * (1.f / DD);
    float var = s2 * (1.f / DD) - mean * mean;
    float inv = rsqrtf(var + 1e-5f);
    float2 g2 = *(const float2*)(gamma + tid * 2);
    float2 b2 = *(const float2*)(beta + tid * 2);
    float2 o;
    o.x = (v.x - mean) * inv * g2.x + b2.x;
    o.y = (v.y - mean) * inv * g2.y + b2.y;
    *(float2*)(out + (size_t)row * DD + tid * 2) = o;
}

// ===========================================================================
extern "C" void kernel_launch(void* const* d_in, const int* in_sizes, int n_in,
                              void* d_out, int out_size)
{
    const float* q  = (const float*)d_in[0];
    const float* k  = (const float*)d_in[1];
    const float* v  = (const float*)d_in[2];
    const float* pe = (const float*)d_in[3];
    const unsigned char* kpm = (const unsigned char*)d_in[4];
    const unsigned char* am  = (const unsigned char*)d_in[5];
    const float* Wq = (const float*)d_in[6];
    const float* bq = (const float*)d_in[7];
    const float* Wk = (const float*)d_in[8];
    const float* bk = (const float*)d_in[9];
    const float* Wv = (const float*)d_in[10];
    const float* bv = (const float*)d_in[11];
    const float* Wo = (const float*)d_in[12];
    const float* bo = (const float*)d_in[13];
    const float* Wr = (const float*)d_in[14];
    const float* br = (const float*)d_in[15];
    const float* ub = (const float*)d_in[16];
    const float* vb = (const float*)d_in[17];
    const float* lg = (const float*)d_in[18];
    const float* lb = (const float*)d_in[19];

    float* normed = (float*)d_out;
    float* attnw  = normed + (size_t)BB * SQL * DD;

    float *qh, *kh, *vh, *att, *o2;
    cudaGetSymbolAddress((void**)&qh,  g_qh);
    cudaGetSymbolAddress((void**)&kh,  g_kh);
    cudaGetSymbolAddress((void**)&vh,  g_vh);
    cudaGetSymbolAddress((void**)&att, g_att);
    cudaGetSymbolAddress((void**)&o2,  g_o2);

    __nv_bfloat16 *qih, *qil, *kih, *kil, *vih, *vil;
    __nv_bfloat16 *wqh, *wql, *wkh, *wkl, *wvh, *wvl, *woh, *wol;
    __nv_bfloat16 *qvh, *qvl, *ath, *atl;
    cudaGetSymbolAddress((void**)&qih, g_qi_h); cudaGetSymbolAddress((void**)&qil, g_qi_l);
    cudaGetSymbolAddress((void**)&kih, g_ki_h); cudaGetSymbolAddress((void**)&kil, g_ki_l);
    cudaGetSymbolAddress((void**)&vih, g_vi_h); cudaGetSymbolAddress((void**)&vil, g_vi_l);
    cudaGetSymbolAddress((void**)&wqh, g_wq_h); cudaGetSymbolAddress((void**)&wql, g_wq_l);
    cudaGetSymbolAddress((void**)&wkh, g_wk_h); cudaGetSymbolAddress((void**)&wkl, g_wk_l);
    cudaGetSymbolAddress((void**)&wvh, g_wv_h); cudaGetSymbolAddress((void**)&wvl, g_wv_l);
    cudaGetSymbolAddress((void**)&woh, g_wo_h); cudaGetSymbolAddress((void**)&wol, g_wo_l);
    cudaGetSymbolAddress((void**)&qvh, g_qv_h); cudaGetSymbolAddress((void**)&qvl, g_qv_l);
    cudaGetSymbolAddress((void**)&ath, g_at_h); cudaGetSymbolAddress((void**)&atl, g_at_l);

    // mask normalization
    zero_flags<<<1, 32>>>();
    mask_detect<<<16, 256>>>(am);
    mask_convert<<<64, 256>>>(am, kpm);

    // operand conversions
    conv_inputs<<<dim3(MR * DD / 4 / 256, 1, 3), 256>>>(q, k, v);
    conv_w<<<dim3(16, 16, 4), dim3(32, 32)>>>(Wq, Wk, Wv, Wo);
    conv_wr<<<DD * DD / 4 / 256, 256>>>(Wr);

    // projections (tensor)
    mma2<<<dim3(8, 32), 256>>>(qih, qil, wqh, wql, bq, nullptr, qh, qvh, qvl, vb);
    mma2<<<dim3(8, 32), 256>>>(kih, kil, wkh, wkl, bk, nullptr, kh, nullptr, nullptr, nullptr);
    mma2<<<dim3(8, 32), 256>>>(vih, vil, wvh, wvl, bv, nullptr, vh, nullptr, nullptr, nullptr);

    c_kernel<<<(MR * HH + 255) / 256, 256>>>(vb, br);
    t_mma<<<dim3(8, 32, 8), 256>>>();

    ac_kernel<<<dim3(8, 8, 32), 256>>>(ub, attnw);
    bd_mma<<<512, 256>>>(pe, attnw);
    softmax_kernel<<<BHH * SQL, 128>>>(attnw);

    av_kernel<<<dim3(8, 32), 256>>>(attnw);

    mma2<<<dim3(8, 32), 256>>>(ath, atl, woh, wol, bo, q, o2, nullptr, nullptr, nullptr);
    ln_kernel<<<MR, 256>>>(o2, lg, lb, normed);
}